// round 1
// baseline (speedup 1.0000x reference)
#include <cuda_runtime.h>
#include <cstdint>

// Problem constants
#define BN      16384
#define DD      65
#define NAA     64
#define NNN     129          // D + NA
#define MM      8385         // N + N(N-1)/2

#define THREADS 512
#define ROWS    128          // rows per block
#define KPT     16           // k-values per thread (64 / 4 threads-per-row)

// Persistent device scratch (allocation-free rule: __device__ globals)
__device__ float  gG[128 * 64];     // combined matrix: rows 0..63 = Wx (x,t pairs), rows 64..127 = M = sym(U)
__device__ float  gwy[64];          // W_pair(i, 64)
__device__ float  gwys[64];         // W_pair(64, 65+k)
__device__ float  gwlt[64];         // wl[65+k]
__device__ float  gwylin;           // wl[64]
__device__ double g_pen[2];         // int_penalty raw sum, neut_penalty sum

// off(i) = start of pair row i in triu enumeration, P(i,j) = off(i) + j - i - 1
__device__ __forceinline__ int pair_off(int i) {
    return NNN + i * (2 * NNN - i - 1) / 2;
}

// ---------------------------------------------------------------------------
// Prep: derive weight structures from main_w; also zero penalty accumulators.
// ---------------------------------------------------------------------------
__global__ void prep_kernel(const float* __restrict__ mw) {
    int tid = blockIdx.x * blockDim.x + threadIdx.x;
    if (tid < 8192) {
        int i = tid >> 6;
        int k = tid & 63;
        float v;
        if (i < 64) {
            // W_pair(i, 65+k) = mw[off(i) + 64 + k - i]
            v = mw[pair_off(i) + 64 + k - i];
        } else {
            int kp = i - 64;
            if (kp == k) {
                v = 0.0f;
            } else {
                int a = kp < k ? kp : k;
                int b = kp < k ? k : kp;
                int ia = 65 + a, jb = 65 + b;
                v = 0.5f * mw[pair_off(ia) + jb - ia - 1];
            }
        }
        gG[tid] = v;
    } else if (tid < 8192 + 64) {
        int i = tid - 8192;
        gwy[i] = mw[pair_off(i) + 63 - i];          // P(i, 64)
    } else if (tid < 8192 + 128) {
        int k = tid - (8192 + 64);
        gwys[k] = mw[pair_off(64) + k];             // P(64, 65+k)
    } else if (tid < 8192 + 192) {
        int k = tid - (8192 + 128);
        gwlt[k] = mw[65 + k];
    } else if (tid == 8192 + 192) {
        gwylin   = mw[64];
        g_pen[0] = 0.0;
        g_pen[1] = 0.0;
    }
}

// Fast accurate tanh: 1 - 2/(1+exp(2w)) via ex2.approx + rcp.approx (~1e-6 abs err)
__device__ __forceinline__ float tanh_fast(float w) {
    float e, r;
    asm("ex2.approx.f32 %0, %1;" : "=f"(e) : "f"(w * 2.885390081777927f)); // 2*log2(e)
    asm("rcp.approx.f32 %0, %1;" : "=f"(r) : "f"(e + 1.0f));
    return fmaf(-2.0f, r, 1.0f);
}

// Shared layout (floats):
//  sWtT : [0, 4160)         thresh_w transposed, [i][k] stride 64, i in 0..64
//  sB   : [4160, 4224)
//  sG   : [4224, 12416)
//  swy  : [12416, 12480)
//  swys : [12480, 12544)
//  swlt : [12544, 12608)
//  sy   : [12608, 12736)
//  sz   : [12736, 29248)    per-row [x(64) | s(64)], stride 129 (odd -> conflict-free)
#define SMEM_FLOATS 29248
#define SMEM_BYTES  (SMEM_FLOATS * 4)

__global__ void __launch_bounds__(THREADS, 1)
main_kernel(const float* __restrict__ inps,
            const float* __restrict__ tw,
            const float* __restrict__ tb,
            float* __restrict__ out) {
    extern __shared__ float sm[];
    float* sWtT = sm;
    float* sB   = sm + 4160;
    float* sG   = sm + 4224;
    float* swy  = sm + 12416;
    float* swys = sm + 12480;
    float* swlt = sm + 12544;
    float* sy   = sm + 12608;
    float* sz   = sm + 12736;

    const int t    = threadIdx.x;
    const int q    = t & 3;          // quarter: which 16 k's this thread owns
    const int r    = t >> 2;         // local row 0..127
    const int k0   = q * KPT;
    const int row0 = blockIdx.x * ROWS;

    // ---- cooperative loads ----
    for (int idx = t; idx < 64 * 65; idx += THREADS) {
        int k = idx / 65, i = idx % 65;
        sWtT[i * 64 + k] = tw[idx];
    }
    for (int idx = t; idx < 64; idx += THREADS) {
        sB[idx]   = tb[idx];
        swy[idx]  = gwy[idx];
        swys[idx] = gwys[idx];
        swlt[idx] = gwlt[idx];
    }
    for (int idx = t; idx < 8192; idx += THREADS) sG[idx] = gG[idx];
    for (int idx = t; idx < ROWS * 65; idx += THREADS) {
        int rr = idx / 65, cc = idx % 65;
        float v = inps[(row0 + rr) * 65 + cc];
        if (cc < 64) sz[rr * 129 + cc] = v;
        else         sy[rr] = v;
    }
    __syncthreads();

    const float* xrow = sz + r * 129;
    const float  yv   = sy[r];

    // ---- Phase A: c_k = x . Wt_row_k  (16 accumulators, w4 broadcast) ----
    float c[KPT];
#pragma unroll
    for (int kk = 0; kk < KPT; kk++) c[kk] = 0.0f;

#pragma unroll 4
    for (int i = 0; i < 64; i++) {
        float xi = xrow[i];
        const float4* w4 = reinterpret_cast<const float4*>(sWtT + i * 64 + k0);
#pragma unroll
        for (int qq = 0; qq < KPT / 4; qq++) {
            float4 w = w4[qq];
            c[4 * qq + 0] = fmaf(xi, w.x, c[4 * qq + 0]);
            c[4 * qq + 1] = fmaf(xi, w.y, c[4 * qq + 1]);
            c[4 * qq + 2] = fmaf(xi, w.z, c[4 * qq + 2]);
            c[4 * qq + 3] = fmaf(xi, w.w, c[4 * qq + 3]);
        }
    }

    // ---- tanh, d/s, penalties, small dots ----
    float d[KPT];
    float accDW = 0.0f, accSW = 0.0f, accI = 0.0f, accN = 0.0f;
#pragma unroll
    for (int kk = 0; kk < KPT; kk++) {
        int   k  = k0 + kk;
        float cv = c[kk] + sB[k];
        float hv = yv * sWtT[64 * 64 + k];
        float w1 = cv + hv;
        float w2 = cv - hv;
        float t1 = tanh_fast(w1);
        float t2 = tanh_fast(w2);
        float dk = t1 - t2;
        float sk = t1 + t2;
        d[kk] = dk;
        sz[r * 129 + 64 + k] = sk;
        accDW = fmaf(dk, swlt[k], accDW);
        accSW = fmaf(sk, swys[k], accSW);
        float e1 = fmaf(-t1, t1, 1.0f);
        float e2 = fmaf(-t2, t2, 1.0f);
        accI = fmaf(e1, e1, accI);
        accI = fmaf(e2, e2, accI);
        float nt = fmaf(t2, w2, -(t1 * w1));
        accN = fmaf(nt, nt, accN);
    }

    // x . wy partial (this thread's 16 indices)
    float accXW = 0.0f;
#pragma unroll
    for (int kk = 0; kk < KPT; kk++) {
        int i = k0 + kk;
        accXW = fmaf(xrow[i], swy[i], accXW);
    }

    __syncwarp();   // s-values written by the 4 partner lanes (same warp)

    // ---- Phase B: g_k = sum_i z_i * G[i][k],  z = [x | s] contiguous in sz ----
    float g[KPT];
#pragma unroll
    for (int kk = 0; kk < KPT; kk++) g[kk] = 0.0f;

#pragma unroll 4
    for (int i = 0; i < 128; i++) {
        float zi = xrow[i];
        const float4* g4 = reinterpret_cast<const float4*>(sG + i * 64 + k0);
#pragma unroll
        for (int qq = 0; qq < KPT / 4; qq++) {
            float4 w = g4[qq];
            g[4 * qq + 0] = fmaf(zi, w.x, g[4 * qq + 0]);
            g[4 * qq + 1] = fmaf(zi, w.y, g[4 * qq + 1]);
            g[4 * qq + 2] = fmaf(zi, w.z, g[4 * qq + 2]);
            g[4 * qq + 3] = fmaf(zi, w.w, g[4 * qq + 3]);
        }
    }

    float gz = 0.0f;
#pragma unroll
    for (int kk = 0; kk < KPT; kk++) gz = fmaf(d[kk], g[kk], gz);

    // ---- combine 4 partner lanes (lanes q, q^1, q^2 are adjacent) ----
    gz    += __shfl_xor_sync(0xffffffffu, gz, 1);
    gz    += __shfl_xor_sync(0xffffffffu, gz, 2);
    accDW += __shfl_xor_sync(0xffffffffu, accDW, 1);
    accDW += __shfl_xor_sync(0xffffffffu, accDW, 2);
    accSW += __shfl_xor_sync(0xffffffffu, accSW, 1);
    accSW += __shfl_xor_sync(0xffffffffu, accSW, 2);
    accXW += __shfl_xor_sync(0xffffffffu, accXW, 1);
    accXW += __shfl_xor_sync(0xffffffffu, accXW, 2);

    if (q == 0) {
        float diff = 1.0f
                   + 2.0f * yv * gwylin
                   + accDW
                   + 2.0f * yv * accXW
                   + yv * accSW
                   + gz;
        out[row0 + r] = diff;
    }

    // ---- global penalty reduction: warp reduce -> double atomics ----
#pragma unroll
    for (int off = 16; off > 0; off >>= 1) {
        accI += __shfl_xor_sync(0xffffffffu, accI, off);
        accN += __shfl_xor_sync(0xffffffffu, accN, off);
    }
    if ((t & 31) == 0) {
        atomicAdd(&g_pen[0], (double)accI);
        atomicAdd(&g_pen[1], (double)accN);
    }
}

__global__ void epi_kernel(float* __restrict__ out, int Bn) {
    out[Bn]     = (float)(g_pen[0] * (1.0 / 300.0));   // GAMMA/300, GAMMA=1
    out[Bn + 1] = (float)(g_pen[1]);
}

extern "C" void kernel_launch(void* const* d_in, const int* in_sizes, int n_in,
                              void* d_out, int out_size) {
    const float* inps = (const float*)d_in[0];
    const float* tw   = (const float*)d_in[1];
    const float* tb   = (const float*)d_in[2];
    const float* mw   = (const float*)d_in[3];
    float* out = (float*)d_out;

    int Bn = in_sizes[0] / 65;

    cudaFuncSetAttribute(main_kernel,
                         cudaFuncAttributeMaxDynamicSharedMemorySize, SMEM_BYTES);

    prep_kernel<<<(8192 + 256 + 255) / 256, 256>>>(mw);
    main_kernel<<<Bn / ROWS, THREADS, SMEM_BYTES>>>(inps, tw, tb, out);
    epi_kernel<<<1, 1>>>(out, Bn);
}

// round 2
// speedup vs baseline: 1.6745x; 1.6745x over previous
#include <cuda_runtime.h>

#define NNN     129          // D + NA
#define THREADS 512
#define ROWS    128          // rows per block
#define KPT     16           // k-values per thread
#define SW      80           // padded row stride (floats) for weight tiles

// ---- persistent device scratch (allocation-free rule) ----
__device__ float        gPartI[256];
__device__ float        gPartN[256];
__device__ unsigned int gCount = 0;

__device__ __forceinline__ int pair_off(int i) {
    return NNN + i * (2 * NNN - i - 1) / 2;
}

// k -> column offset inside an 80-float weight row (4 segments of 16 @ 20-float pitch)
__device__ __forceinline__ int koff(int k) {
    return (k >> 4) * 20 + (k & 15);
}

// packed f32x2 helpers
__device__ __forceinline__ unsigned long long pack2(float x) {
    unsigned long long r;
    asm("mov.b64 %0, {%1, %1};" : "=l"(r) : "f"(x));
    return r;
}
__device__ __forceinline__ void unpack2(unsigned long long v, float& a, float& b) {
    asm("mov.b64 {%0, %1}, %2;" : "=f"(a), "=f"(b) : "l"(v));
}
#define FMA2(acc, a, b) asm("fma.rn.f32x2 %0, %1, %2, %0;" : "+l"(acc) : "l"(a), "l"(b))

// fast tanh: 1 - 2/(1+exp(2w)) via ex2.approx + rcp.approx
__device__ __forceinline__ float tanh_fast(float w) {
    float e, r;
    asm("ex2.approx.f32 %0, %1;" : "=f"(e) : "f"(w * 2.885390081777927f));
    asm("rcp.approx.f32 %0, %1;" : "=f"(r) : "f"(e + 1.0f));
    return fmaf(-2.0f, r, 1.0f);
}

// Shared layout (float offsets):
//  sWtT : [0, 5120)        64 rows x 80 (x-part of thresh_w, transposed, segmented)
//  sG   : [5120, 15360)    128 rows x 80 (combined pair matrix, segmented)
//  sWy  : [15360, 15424)   thresh_w y-column
//  sB   : [15424, 15488)
//  swy  : [15488, 15552)   P(i,64)
//  swys : [15552, 15616)   P(64,65+k)
//  swlt : [15616, 15680)   wl[65+k]
//  sy   : [15680, 15808)
//  sMisc: [15808, 15824)   [0]=wl[64], [1]=last-block flag
//  sRed : [15824, 15856)   16 warps x 2
//  sz   : [15856, 32368)   per-row [x(64)|s(64)], stride 129 (odd -> conflict-free)
#define SMEM_FLOATS 32368
#define SMEM_BYTES  (SMEM_FLOATS * 4)

__global__ void __launch_bounds__(THREADS, 1)
fused_kernel(const float* __restrict__ inps,
             const float* __restrict__ tw,
             const float* __restrict__ tb,
             const float* __restrict__ mw,
             float* __restrict__ out,
             int Bn) {
    extern __shared__ float sm[];
    float* sWtT  = sm;
    float* sG    = sm + 5120;
    float* sWy   = sm + 15360;
    float* sB    = sm + 15424;
    float* swy   = sm + 15488;
    float* swys  = sm + 15552;
    float* swlt  = sm + 15616;
    float* sy    = sm + 15680;
    float* sMisc = sm + 15808;
    float* sRed  = sm + 15824;
    float* sz    = sm + 15856;

    const int t    = threadIdx.x;
    const int q    = t & 3;
    const int r    = t >> 2;
    const int k0   = q * KPT;
    const int row0 = blockIdx.x * ROWS;

    // ---------------- load / prep phase ----------------
    // thresh_w x-part transposed into segmented layout
    for (int idx = t; idx < 64 * 64; idx += THREADS) {
        int k = idx >> 6, i = idx & 63;
        sWtT[i * SW + koff(k)] = tw[k * 65 + i];
    }
    for (int idx = t; idx < 64; idx += THREADS) {
        sWy[idx]  = tw[idx * 65 + 64];
        sB[idx]   = tb[idx];
        swy[idx]  = mw[pair_off(idx) + 63 - idx];
        swlt[idx] = mw[65 + idx];
        swys[idx] = mw[pair_off(64) + idx];
    }
    if (t == 0) sMisc[0] = mw[64];
    // combined G matrix (rows 0..63: x<->t pair weights, rows 64..127: sym(U_tt))
    for (int idx = t; idx < 8192; idx += THREADS) {
        int i = idx >> 6, k = idx & 63;
        float v;
        if (i < 64) {
            v = mw[pair_off(i) + 64 + k - i];
        } else {
            int kp = i - 64;
            if (kp == k) v = 0.0f;
            else {
                int a = kp < k ? kp : k;
                int b = kp < k ? k : kp;
                int ia = 65 + a, jb = 65 + b;
                v = 0.5f * mw[pair_off(ia) + jb - ia - 1];
            }
        }
        sG[i * SW + koff(k)] = v;
    }
    // inputs
    for (int idx = t; idx < ROWS * 65; idx += THREADS) {
        int rr = idx / 65, cc = idx - rr * 65;
        float v = inps[(row0 + rr) * 65 + cc];
        if (cc < 64) sz[rr * NNN + cc] = v;
        else         sy[rr] = v;
    }
    __syncthreads();

    const float* xrow = sz + r * NNN;
    const float  yv   = sy[r];

    // ---------------- Phase A: c = x . Wt (packed f32x2) ----------------
    unsigned long long c[8];
#pragma unroll
    for (int j = 0; j < 8; j++) c[j] = 0ULL;

#pragma unroll 4
    for (int i = 0; i < 64; i++) {
        unsigned long long xp = pack2(xrow[i]);
        const ulonglong2* w2 = reinterpret_cast<const ulonglong2*>(sWtT + i * SW + q * 20);
        ulonglong2 w0 = w2[0], w1 = w2[1], w2v = w2[2], w3 = w2[3];
        FMA2(c[0], xp, w0.x); FMA2(c[1], xp, w0.y);
        FMA2(c[2], xp, w1.x); FMA2(c[3], xp, w1.y);
        FMA2(c[4], xp, w2v.x); FMA2(c[5], xp, w2v.y);
        FMA2(c[6], xp, w3.x); FMA2(c[7], xp, w3.y);
    }

    // ---------------- tanh / penalties / small dots ----------------
    float d[KPT];
    float accDW = 0.0f, accSW = 0.0f, accI = 0.0f, accN = 0.0f;
#pragma unroll
    for (int j = 0; j < 8; j++) {
        float ca, cb;
        unpack2(c[j], ca, cb);
#pragma unroll
        for (int h = 0; h < 2; h++) {
            int   kk = 2 * j + h;
            int   k  = k0 + kk;
            float cv = (h == 0 ? ca : cb) + sB[k];
            float hv = yv * sWy[k];
            float w1s = cv + hv;
            float w2s = cv - hv;
            float t1 = tanh_fast(w1s);
            float t2 = tanh_fast(w2s);
            float dk = t1 - t2;
            float sk = t1 + t2;
            d[kk] = dk;
            sz[r * NNN + 64 + k] = sk;
            accDW = fmaf(dk, swlt[k], accDW);
            accSW = fmaf(sk, swys[k], accSW);
            float e1 = fmaf(-t1, t1, 1.0f);
            float e2 = fmaf(-t2, t2, 1.0f);
            accI = fmaf(e1, e1, accI);
            accI = fmaf(e2, e2, accI);
            float nt = fmaf(t2, w2s, -(t1 * w1s));
            accN = fmaf(nt, nt, accN);
        }
    }

    float accXW = 0.0f;
#pragma unroll
    for (int kk = 0; kk < KPT; kk++) {
        int i = k0 + kk;
        accXW = fmaf(xrow[i], swy[i], accXW);
    }

    __syncwarp();   // partner lanes' s-values (same warp)

    // ---------------- Phase B: g = z . G (packed f32x2) ----------------
    unsigned long long g[8];
#pragma unroll
    for (int j = 0; j < 8; j++) g[j] = 0ULL;

#pragma unroll 4
    for (int i = 0; i < 128; i++) {
        unsigned long long zp = pack2(xrow[i]);
        const ulonglong2* w2 = reinterpret_cast<const ulonglong2*>(sG + i * SW + q * 20);
        ulonglong2 w0 = w2[0], w1 = w2[1], w2v = w2[2], w3 = w2[3];
        FMA2(g[0], zp, w0.x); FMA2(g[1], zp, w0.y);
        FMA2(g[2], zp, w1.x); FMA2(g[3], zp, w1.y);
        FMA2(g[4], zp, w2v.x); FMA2(g[5], zp, w2v.y);
        FMA2(g[6], zp, w3.x); FMA2(g[7], zp, w3.y);
    }

    float gz = 0.0f;
#pragma unroll
    for (int j = 0; j < 8; j++) {
        float ga, gb;
        unpack2(g[j], ga, gb);
        gz = fmaf(d[2 * j],     ga, gz);
        gz = fmaf(d[2 * j + 1], gb, gz);
    }

    // ---------------- combine 4 partner lanes ----------------
    gz    += __shfl_xor_sync(0xffffffffu, gz, 1);
    gz    += __shfl_xor_sync(0xffffffffu, gz, 2);
    accDW += __shfl_xor_sync(0xffffffffu, accDW, 1);
    accDW += __shfl_xor_sync(0xffffffffu, accDW, 2);
    accSW += __shfl_xor_sync(0xffffffffu, accSW, 1);
    accSW += __shfl_xor_sync(0xffffffffu, accSW, 2);
    accXW += __shfl_xor_sync(0xffffffffu, accXW, 1);
    accXW += __shfl_xor_sync(0xffffffffu, accXW, 2);

    if (q == 0) {
        float diff = 1.0f
                   + 2.0f * yv * sMisc[0]
                   + accDW
                   + 2.0f * yv * accXW
                   + yv * accSW
                   + gz;
        out[row0 + r] = diff;
    }

    // ---------------- penalty reduction ----------------
#pragma unroll
    for (int off = 16; off > 0; off >>= 1) {
        accI += __shfl_xor_sync(0xffffffffu, accI, off);
        accN += __shfl_xor_sync(0xffffffffu, accN, off);
    }
    if ((t & 31) == 0) {
        sRed[t >> 5]      = accI;
        sRed[16 + (t >> 5)] = accN;
    }
    __syncthreads();
    if (t == 0) {
        float pI = 0.0f, pN = 0.0f;
#pragma unroll
        for (int w = 0; w < 16; w++) { pI += sRed[w]; pN += sRed[16 + w]; }
        gPartI[blockIdx.x] = pI;
        gPartN[blockIdx.x] = pN;
        __threadfence();
        unsigned int tk = atomicAdd(&gCount, 1u);
        sMisc[1] = (tk == gridDim.x - 1) ? 1.0f : 0.0f;
    }
    __syncthreads();

    // last block finishes the global reduction
    if (sMisc[1] != 0.0f && t < 32) {
        __threadfence();
        double sI = 0.0, sN = 0.0;
        for (int i = t; i < (int)gridDim.x; i += 32) {
            sI += (double)gPartI[i];
            sN += (double)gPartN[i];
        }
#pragma unroll
        for (int off = 16; off > 0; off >>= 1) {
            sI += __shfl_xor_sync(0xffffffffu, sI, off);
            sN += __shfl_xor_sync(0xffffffffu, sN, off);
        }
        if (t == 0) {
            out[Bn]     = (float)(sI * (1.0 / 300.0));
            out[Bn + 1] = (float)sN;
            gCount = 0;   // reset for next graph replay
        }
    }
}

extern "C" void kernel_launch(void* const* d_in, const int* in_sizes, int n_in,
                              void* d_out, int out_size) {
    const float* inps = (const float*)d_in[0];
    const float* tw   = (const float*)d_in[1];
    const float* tb   = (const float*)d_in[2];
    const float* mw   = (const float*)d_in[3];
    float* out = (float*)d_out;

    int Bn = in_sizes[0] / 65;

    cudaFuncSetAttribute(fused_kernel,
                         cudaFuncAttributeMaxDynamicSharedMemorySize, SMEM_BYTES);

    fused_kernel<<<Bn / ROWS, THREADS, SMEM_BYTES>>>(inps, tw, tb, mw, out, Bn);
}